// round 14
// baseline (speedup 1.0000x reference)
#include <cuda_runtime.h>
#include <cuda_fp16.h>

#define BATCH 8
#define HH 512
#define WW 512
#define W2 (WW / 2)
#define PLANE (HH * WW)
#define NP (BATCH * PLANE)
#define RAD 15
#define INV_K2 (1.0f / 961.0f)
#define EPSV 1e-6f
#define SEG 16        // rows per vertical segment (k_v2)
#define SEGV 16       // rows per vertical segment (k_vh)
#define SPAD 544
#define PADI(i) ((i) + ((i) >> 4))

// -------- scratch (device globals) --------
// 0=I, 1=I*I, 2..4=p_c, 5..7=I*p_c   (fp16 planes, fp32 accumulation downstream)
__device__ __half g_hsum[8][NP];   // 32 MB
__device__ __half g_gray[NP];      // 4 MB
__device__ __half g_hsum2[6][NP];  // 24 MB

__device__ __forceinline__ float iscan(float v, int lane) {
#pragma unroll
    for (int o = 1; o < 32; o <<= 1) {
        float n = __shfl_up_sync(0xffffffffu, v, o);
        if (lane >= o) v += n;
    }
    return v;
}

// load 4 consecutive halves (8B aligned) as float4
__device__ __forceinline__ float4 ldh4(const __half* p, int idx) {
    uint2 r = *reinterpret_cast<const uint2*>(p + idx);
    __half2 h0 = *reinterpret_cast<__half2*>(&r.x);
    __half2 h1 = *reinterpret_cast<__half2*>(&r.y);
    float2 f0 = __half22float2(h0), f1 = __half22float2(h1);
    return make_float4(f0.x, f0.y, f1.x, f1.y);
}

// ============================================================================
// K1: horizontal pass (R12 config — best measured, 23.5us). Chunk-local scan,
// register-direct loads, coalesced fp16 stores. 1 warp/row, 4 rows/block.
// ============================================================================
__global__ __launch_bounds__(128) void k_h1(const float* __restrict__ guide,
                                            const float* __restrict__ input) {
    const int warp = threadIdx.x >> 5;
    const int lane = threadIdx.x & 31;
    const int grow = blockIdx.x * 4 + warp;
    const int b = grow >> 9;
    const int r = grow & 511;

    const float* gR = guide + ((size_t)(b * 3 + 0) * HH + r) * WW;
    const float* gG = guide + ((size_t)(b * 3 + 1) * HH + r) * WW;
    const float* gB = guide + ((size_t)(b * 3 + 2) * HH + r) * WW;
    const float* p0 = input + ((size_t)(b * 3 + 0) * HH + r) * WW;
    const float* p1 = input + ((size_t)(b * 3 + 1) * HH + r) * WW;
    const float* p2 = input + ((size_t)(b * 3 + 2) * HH + r) * WW;

    __shared__ float sp[4][SPAD];
    float* pref = sp[warp];

    const size_t rowOff = (size_t)grow * WW;
    const int cb = lane * 16;

    float gv[16], pv[16], lp[16];

#pragma unroll
    for (int j = 0; j < 4; j++) {
        float4 rv = ((const float4*)(gR + cb))[j];
        float4 gg = ((const float4*)(gG + cb))[j];
        float4 bv = ((const float4*)(gB + cb))[j];
        gv[4*j+0] = 0.299f * rv.x + 0.587f * gg.x + 0.114f * bv.x;
        gv[4*j+1] = 0.299f * rv.y + 0.587f * gg.y + 0.114f * bv.y;
        gv[4*j+2] = 0.299f * rv.z + 0.587f * gg.z + 0.114f * bv.z;
        gv[4*j+3] = 0.299f * rv.w + 0.587f * gg.w + 0.114f * bv.w;
    }
    {
        __half2 h[8];
#pragma unroll
        for (int j = 0; j < 8; j++) h[j] = __floats2half2_rn(gv[2*j], gv[2*j+1]);
        uint4* dst = reinterpret_cast<uint4*>(g_gray + rowOff + cb);
        dst[0] = *reinterpret_cast<uint4*>(&h[0]);
        dst[1] = *reinterpret_cast<uint4*>(&h[4]);
    }

    auto scan_store = [&](__half* __restrict__ outp) {
        float tot = lp[15];
        float ex = iscan(tot, lane) - tot;
#pragma unroll
        for (int k = 0; k < 16; k++) pref[PADI(cb + k)] = ex + lp[k];
        __syncwarp();
#pragma unroll
        for (int i = 0; i < 16; i++) {
            int x = i * 32 + lane;
            int hx = (x + RAD > WW - 1) ? (WW - 1) : (x + RAD);
            float hi = pref[PADI(hx)];
            float lo = (x >= RAD + 1) ? pref[PADI(x - RAD - 1)] : 0.f;
            outp[x] = __float2half_rn(hi - lo);
        }
        __syncwarp();
    };

    { float a = 0.f;
#pragma unroll
      for (int k = 0; k < 16; k++) { a += gv[k]; lp[k] = a; } }
    scan_store(g_hsum[0] + rowOff);
    { float a = 0.f;
#pragma unroll
      for (int k = 0; k < 16; k++) { a += gv[k] * gv[k]; lp[k] = a; } }
    scan_store(g_hsum[1] + rowOff);

    const float* pc[3] = { p0, p1, p2 };
    const int qp[3] = { 2, 3, 4 };
    const int qip[3] = { 5, 6, 7 };
#pragma unroll
    for (int c = 0; c < 3; c++) {
#pragma unroll
        for (int j = 0; j < 4; j++) {
            float4 v = ((const float4*)(pc[c] + cb))[j];
            pv[4*j+0] = v.x; pv[4*j+1] = v.y; pv[4*j+2] = v.z; pv[4*j+3] = v.w;
        }
        { float a = 0.f;
#pragma unroll
          for (int k = 0; k < 16; k++) { a += pv[k]; lp[k] = a; } }
        scan_store(g_hsum[qp[c]] + rowOff);
        { float a = 0.f;
#pragma unroll
          for (int k = 0; k < 16; k++) { a += gv[k] * pv[k]; lp[k] = a; } }
        scan_store(g_hsum[qip[c]] + rowOff);
    }
}

// ============================================================================
// K2 (fused vertical+horizontal on a,b): 256 thr, 2 cols/thread, SEGV=16.
// NEW: TWO ROWS per scan round -> 12 quantities per barrier pair, halving
// barrier count (32 -> 16 per block) and doubling scan ILP. Single-buffered
// smem (the 2-barrier structure already orders reads before next writes).
// grid (32, 8) = 256 blocks.
// ============================================================================
__global__ __launch_bounds__(256) void k_vh() {
    const int tid  = threadIdx.x;
    const int warp = tid >> 5;
    const int lane = tid & 31;
    const int r0 = blockIdx.x * SEGV;
    const int b  = blockIdx.y;
    const int base = b * (PLANE / 2) + tid;   // half2 index

    __shared__ float s_pref[12][WW];   // 24 KB
    __shared__ float s_wtot[12][8];

    float2 s[8];
#pragma unroll
    for (int q = 0; q < 8; q++) { s[q].x = 0.f; s[q].y = 0.f; }

    const int jstart = (r0 - RAD < 0) ? 0 : (r0 - RAD);
#pragma unroll 4
    for (int j = jstart; j <= r0 + RAD; j++) {
        const int off = base + j * W2;
#pragma unroll
        for (int q = 0; q < 8; q++) {
            float2 v = __half22float2(((const __half2*)g_hsum[q])[off]);
            s[q].x += v.x; s[q].y += v.y;
        }
    }

    for (int i = 0; i < SEGV; i += 2) {
        const int row0 = r0 + i;
        const int row1 = row0 + 1;
        const int off0 = base + row0 * W2;
        const int off1 = base + row1 * W2;

        // ---- prefetch both rows' slide loads ----
        const int ld0 = row0 + RAD + 1, tr0 = row0 - RAD;
        const int ld1 = row1 + RAD + 1, tr1 = row1 - RAD;
        const bool hl0 = ld0 < HH, ht0 = tr0 >= 0;
        const bool hl1 = ld1 < HH, ht1 = tr1 >= 0;
        float2 L0[8], T0[8], L1[8], T1[8];
        if (hl0) { const int o = base + ld0 * W2;
#pragma unroll
            for (int q = 0; q < 8; q++) L0[q] = __half22float2(((const __half2*)g_hsum[q])[o]); }
        if (ht0) { const int o = base + tr0 * W2;
#pragma unroll
            for (int q = 0; q < 8; q++) T0[q] = __half22float2(((const __half2*)g_hsum[q])[o]); }
        if (hl1) { const int o = base + ld1 * W2;
#pragma unroll
            for (int q = 0; q < 8; q++) L1[q] = __half22float2(((const __half2*)g_hsum[q])[o]); }
        if (ht1) { const int o = base + tr1 * W2;
#pragma unroll
            for (int q = 0; q < 8; q++) T1[q] = __half22float2(((const __half2*)g_hsum[q])[o]); }

        // ---- a,b for both rows (advance window in registers between) ----
        float2 ab[12];
        {
            float mIx = s[0].x * INV_K2, mIy = s[0].y * INV_K2;
            float cIx = s[1].x * INV_K2, cIy = s[1].y * INV_K2;
            float ivx = 1.f / (cIx - mIx * mIx + EPSV);
            float ivy = 1.f / (cIy - mIy * mIy + EPSV);
#pragma unroll
            for (int c = 0; c < 3; c++) {
                float mpx  = s[2 + c].x * INV_K2, mpy  = s[2 + c].y * INV_K2;
                float cIpx = s[5 + c].x * INV_K2, cIpy = s[5 + c].y * INV_K2;
                float ax = (cIpx - mIx * mpx) * ivx;
                float ay = (cIpy - mIy * mpy) * ivy;
                ab[c].x = ax;                 ab[c].y = ay;
                ab[3 + c].x = mpx - ax * mIx; ab[3 + c].y = mpy - ay * mIy;
            }
        }
        if (hl0) {
#pragma unroll
            for (int q = 0; q < 8; q++) { s[q].x += L0[q].x; s[q].y += L0[q].y; }
        }
        if (ht0) {
#pragma unroll
            for (int q = 0; q < 8; q++) { s[q].x -= T0[q].x; s[q].y -= T0[q].y; }
        }
        {
            float mIx = s[0].x * INV_K2, mIy = s[0].y * INV_K2;
            float cIx = s[1].x * INV_K2, cIy = s[1].y * INV_K2;
            float ivx = 1.f / (cIx - mIx * mIx + EPSV);
            float ivy = 1.f / (cIy - mIy * mIy + EPSV);
#pragma unroll
            for (int c = 0; c < 3; c++) {
                float mpx  = s[2 + c].x * INV_K2, mpy  = s[2 + c].y * INV_K2;
                float cIpx = s[5 + c].x * INV_K2, cIpy = s[5 + c].y * INV_K2;
                float ax = (cIpx - mIx * mpx) * ivx;
                float ay = (cIpy - mIy * mpy) * ivy;
                ab[6 + c].x = ax;                 ab[6 + c].y = ay;
                ab[9 + c].x = mpx - ax * mIx;     ab[9 + c].y = mpy - ay * mIy;
            }
        }
        if (hl1) {
#pragma unroll
            for (int q = 0; q < 8; q++) { s[q].x += L1[q].x; s[q].y += L1[q].y; }
        }
        if (ht1) {
#pragma unroll
            for (int q = 0; q < 8; q++) { s[q].x -= T1[q].x; s[q].y -= T1[q].y; }
        }

        // ---- one scan round for 12 quantities (2 barriers total) ----
        float tq[12], wv[12];
#pragma unroll
        for (int q = 0; q < 12; q++) {
            tq[q] = ab[q].x + ab[q].y;
            wv[q] = iscan(tq[q], lane);
            if (lane == 31) s_wtot[q][warp] = wv[q];
        }
        __syncthreads();
#pragma unroll
        for (int q = 0; q < 12; q++) {
            float carry = 0.f;
#pragma unroll
            for (int w = 0; w < 7; w++) if (w < warp) carry += s_wtot[q][w];
            float ex = wv[q] - tq[q] + carry;
            float2 pr;
            pr.x = ex + ab[q].x;
            pr.y = pr.x + ab[q].y;
            ((float2*)s_pref[q])[tid] = pr;
        }
        __syncthreads();

        // ---- horizontal box sums for both rows -> g_hsum2 ----
        const int x0 = 2 * tid, x1 = x0 + 1;
        const int h0 = (x0 + RAD > WW - 1) ? (WW - 1) : (x0 + RAD);
        const int h1 = (x1 + RAD > WW - 1) ? (WW - 1) : (x1 + RAD);
        const bool hasL0 = (x0 >= RAD + 1);
        const int lx0 = hasL0 ? (x0 - RAD - 1) : 0;
        const int lx1 = x1 - RAD - 1;   // valid iff x1 >= 16, i.e. hasL1
        const bool hasL1 = (x1 >= RAD + 1);
#pragma unroll
        for (int q = 0; q < 6; q++) {
            float lo0 = hasL0 ? s_pref[q][lx0] : 0.f;
            float lo1 = hasL1 ? s_pref[q][lx1] : 0.f;
            __half2 hv = __floats2half2_rn(s_pref[q][h0] - lo0,
                                           s_pref[q][h1] - lo1);
            ((__half2*)g_hsum2[q])[off0] = hv;

            float mo0 = hasL0 ? s_pref[q + 6][lx0] : 0.f;
            float mo1 = hasL1 ? s_pref[q + 6][lx1] : 0.f;
            __half2 hw = __floats2half2_rn(s_pref[q + 6][h0] - mo0,
                                           s_pref[q + 6][h1] - mo1);
            ((__half2*)g_hsum2[q])[off1] = hw;
        }
    }
}

// ============================================================================
// K3: vertical running sums on fp16 hsum2 (4 cols/thread, fp32 accumulators),
// per channel, fused output. grid (1, HH/SEG, BATCH*3) = 768 blocks. [frozen]
// ============================================================================
__global__ __launch_bounds__(128) void k_v2(float* __restrict__ out) {
    const int t  = threadIdx.x;
    const int zc = blockIdx.z;
    const int b  = zc / 3;
    const int c  = zc - b * 3;
    const int r0 = blockIdx.y * SEG;
    const int baseh = b * PLANE + 4 * t;

    const __half* __restrict__ pa = g_hsum2[c];
    const __half* __restrict__ pb = g_hsum2[3 + c];
    const __half* __restrict__ pg = g_gray;
    float4* __restrict__ po = (float4*)(out + (size_t)zc * PLANE);

    float4 sa = make_float4(0.f, 0.f, 0.f, 0.f);
    float4 sb = make_float4(0.f, 0.f, 0.f, 0.f);

    const int jstart = (r0 - RAD < 0) ? 0 : (r0 - RAD);
#pragma unroll 4
    for (int j = jstart; j <= r0 + RAD; j++) {
        const int off = baseh + j * WW;
        float4 va = ldh4(pa, off), vb = ldh4(pb, off);
        sa.x += va.x; sa.y += va.y; sa.z += va.z; sa.w += va.w;
        sb.x += vb.x; sb.y += vb.y; sb.z += vb.z; sb.w += vb.w;
    }

#pragma unroll 4
    for (int i = 0; i < SEG; i++) {
        const int row = r0 + i;
        const int off = baseh + row * WW;

        const int lead  = row + RAD + 1;
        const int trail = row - RAD;
        const bool hl = lead < HH;
        const bool ht = trail >= 0;
        float4 la, lb, ta, tb;
        if (hl) {
            const int lo = baseh + lead * WW;
            la = ldh4(pa, lo); lb = ldh4(pb, lo);
        }
        if (ht) {
            const int to = baseh + trail * WW;
            ta = ldh4(pa, to); tb = ldh4(pb, to);
        }

        const float4 gr = ldh4(pg, off);
        float4 o;
        o.x = (sa.x * INV_K2) * gr.x + sb.x * INV_K2;
        o.y = (sa.y * INV_K2) * gr.y + sb.y * INV_K2;
        o.z = (sa.z * INV_K2) * gr.z + sb.z * INV_K2;
        o.w = (sa.w * INV_K2) * gr.w + sb.w * INV_K2;
        po[(size_t)row * (WW / 4) + t] = o;

        if (hl) {
            sa.x += la.x; sa.y += la.y; sa.z += la.z; sa.w += la.w;
            sb.x += lb.x; sb.y += lb.y; sb.z += lb.z; sb.w += lb.w;
        }
        if (ht) {
            sa.x -= ta.x; sa.y -= ta.y; sa.z -= ta.z; sa.w -= ta.w;
            sb.x -= tb.x; sb.y -= tb.y; sb.z -= tb.z; sb.w -= tb.w;
        }
    }
}

// ============================================================================
extern "C" void kernel_launch(void* const* d_in, const int* in_sizes, int n_in,
                              void* d_out, int out_size) {
    const float* guide = (const float*)d_in[0];
    const float* input = (const float*)d_in[1];
    float* out = (float*)d_out;

    k_h1<<<BATCH * HH / 4, 128>>>(guide, input);
    k_vh<<<dim3(HH / SEGV, BATCH), 256>>>();
    k_v2<<<dim3(1, HH / SEG, BATCH * 3), 128>>>(out);
}

// round 15
// speedup vs baseline: 1.2478x; 1.2478x over previous
#include <cuda_runtime.h>
#include <cuda_fp16.h>

#define BATCH 8
#define HH 512
#define WW 512
#define W2 (WW / 2)
#define PLANE (HH * WW)
#define NP (BATCH * PLANE)
#define RAD 15
#define INV_K2 (1.0f / 961.0f)
#define EPSV 1e-6f
#define SEG 16        // rows per vertical segment (k_v2)
#define SEGV 16       // rows per vertical segment (k_vh)
#define SPAD 544
#define PADI(i) ((i) + ((i) >> 4))

// -------- scratch (device globals) --------
// 0=I, 1=I*I, 2..4=p_c, 5..7=I*p_c   (fp16 planes, fp32 accumulation downstream)
__device__ __half g_hsum[8][NP];   // 32 MB
__device__ __half g_gray[NP];      // 4 MB
__device__ __half g_hsum2[6][NP];  // 24 MB

__device__ __forceinline__ float iscan(float v, int lane) {
#pragma unroll
    for (int o = 1; o < 32; o <<= 1) {
        float n = __shfl_up_sync(0xffffffffu, v, o);
        if (lane >= o) v += n;
    }
    return v;
}

// ============================================================================
// K1: horizontal pass (R12 config — best measured). Chunk-local scan,
// register-direct loads, coalesced fp16 stores. 1 warp/row, 4 rows/block.
// ============================================================================
__global__ __launch_bounds__(128) void k_h1(const float* __restrict__ guide,
                                            const float* __restrict__ input) {
    const int warp = threadIdx.x >> 5;
    const int lane = threadIdx.x & 31;
    const int grow = blockIdx.x * 4 + warp;
    const int b = grow >> 9;
    const int r = grow & 511;

    const float* gR = guide + ((size_t)(b * 3 + 0) * HH + r) * WW;
    const float* gG = guide + ((size_t)(b * 3 + 1) * HH + r) * WW;
    const float* gB = guide + ((size_t)(b * 3 + 2) * HH + r) * WW;
    const float* p0 = input + ((size_t)(b * 3 + 0) * HH + r) * WW;
    const float* p1 = input + ((size_t)(b * 3 + 1) * HH + r) * WW;
    const float* p2 = input + ((size_t)(b * 3 + 2) * HH + r) * WW;

    __shared__ float sp[4][SPAD];
    float* pref = sp[warp];

    const size_t rowOff = (size_t)grow * WW;
    const int cb = lane * 16;

    float gv[16], pv[16], lp[16];

#pragma unroll
    for (int j = 0; j < 4; j++) {
        float4 rv = ((const float4*)(gR + cb))[j];
        float4 gg = ((const float4*)(gG + cb))[j];
        float4 bv = ((const float4*)(gB + cb))[j];
        gv[4*j+0] = 0.299f * rv.x + 0.587f * gg.x + 0.114f * bv.x;
        gv[4*j+1] = 0.299f * rv.y + 0.587f * gg.y + 0.114f * bv.y;
        gv[4*j+2] = 0.299f * rv.z + 0.587f * gg.z + 0.114f * bv.z;
        gv[4*j+3] = 0.299f * rv.w + 0.587f * gg.w + 0.114f * bv.w;
    }
    {
        __half2 h[8];
#pragma unroll
        for (int j = 0; j < 8; j++) h[j] = __floats2half2_rn(gv[2*j], gv[2*j+1]);
        uint4* dst = reinterpret_cast<uint4*>(g_gray + rowOff + cb);
        dst[0] = *reinterpret_cast<uint4*>(&h[0]);
        dst[1] = *reinterpret_cast<uint4*>(&h[4]);
    }

    auto scan_store = [&](__half* __restrict__ outp) {
        float tot = lp[15];
        float ex = iscan(tot, lane) - tot;
#pragma unroll
        for (int k = 0; k < 16; k++) pref[PADI(cb + k)] = ex + lp[k];
        __syncwarp();
#pragma unroll
        for (int i = 0; i < 16; i++) {
            int x = i * 32 + lane;
            int hx = (x + RAD > WW - 1) ? (WW - 1) : (x + RAD);
            float hi = pref[PADI(hx)];
            float lo = (x >= RAD + 1) ? pref[PADI(x - RAD - 1)] : 0.f;
            outp[x] = __float2half_rn(hi - lo);
        }
        __syncwarp();
    };

    { float a = 0.f;
#pragma unroll
      for (int k = 0; k < 16; k++) { a += gv[k]; lp[k] = a; } }
    scan_store(g_hsum[0] + rowOff);
    { float a = 0.f;
#pragma unroll
      for (int k = 0; k < 16; k++) { a += gv[k] * gv[k]; lp[k] = a; } }
    scan_store(g_hsum[1] + rowOff);

    const float* pc[3] = { p0, p1, p2 };
    const int qp[3] = { 2, 3, 4 };
    const int qip[3] = { 5, 6, 7 };
#pragma unroll
    for (int c = 0; c < 3; c++) {
#pragma unroll
        for (int j = 0; j < 4; j++) {
            float4 v = ((const float4*)(pc[c] + cb))[j];
            pv[4*j+0] = v.x; pv[4*j+1] = v.y; pv[4*j+2] = v.z; pv[4*j+3] = v.w;
        }
        { float a = 0.f;
#pragma unroll
          for (int k = 0; k < 16; k++) { a += pv[k]; lp[k] = a; } }
        scan_store(g_hsum[qp[c]] + rowOff);
        { float a = 0.f;
#pragma unroll
          for (int k = 0; k < 16; k++) { a += gv[k] * pv[k]; lp[k] = a; } }
        scan_store(g_hsum[qip[c]] + rowOff);
    }
}

// ============================================================================
// K2 (fused vertical+horizontal on a,b): FROZEN R12 form. 256 thr,
// 2 cols/thread (half2 loads, fp32 accum), SEGV=16, 2 barriers/row,
// double-buffered smem, slide prefetch. grid (32, 8) = 256 blocks.
// ============================================================================
__global__ __launch_bounds__(256) void k_vh() {
    const int tid  = threadIdx.x;
    const int warp = tid >> 5;
    const int lane = tid & 31;
    const int r0 = blockIdx.x * SEGV;
    const int b  = blockIdx.y;
    const int base = b * (PLANE / 2) + tid;   // half2 index

    __shared__ float s_pref[2][6][WW];   // 24 KB
    __shared__ float s_wtot[2][6][8];

    float2 s[8];
#pragma unroll
    for (int q = 0; q < 8; q++) { s[q].x = 0.f; s[q].y = 0.f; }

    const int jstart = (r0 - RAD < 0) ? 0 : (r0 - RAD);
#pragma unroll 4
    for (int j = jstart; j <= r0 + RAD; j++) {
        const int off = base + j * W2;
#pragma unroll
        for (int q = 0; q < 8; q++) {
            float2 v = __half22float2(((const __half2*)g_hsum[q])[off]);
            s[q].x += v.x; s[q].y += v.y;
        }
    }

    for (int i = 0; i < SEGV; i++) {
        const int row = r0 + i;
        const int off = base + row * W2;
        const int bu = i & 1;

        const int lead  = row + RAD + 1;
        const int trail = row - RAD;
        const bool hl = lead < HH;
        const bool ht = trail >= 0;
        float2 ldv[8], trv[8];
        if (hl) {
            const int lo = base + lead * W2;
#pragma unroll
            for (int q = 0; q < 8; q++)
                ldv[q] = __half22float2(((const __half2*)g_hsum[q])[lo]);
        }
        if (ht) {
            const int to = base + trail * W2;
#pragma unroll
            for (int q = 0; q < 8; q++)
                trv[q] = __half22float2(((const __half2*)g_hsum[q])[to]);
        }

        float2 ab[6];
        {
            float mIx = s[0].x * INV_K2, mIy = s[0].y * INV_K2;
            float cIx = s[1].x * INV_K2, cIy = s[1].y * INV_K2;
            float ivx = 1.f / (cIx - mIx * mIx + EPSV);
            float ivy = 1.f / (cIy - mIy * mIy + EPSV);
#pragma unroll
            for (int c = 0; c < 3; c++) {
                float mpx  = s[2 + c].x * INV_K2, mpy  = s[2 + c].y * INV_K2;
                float cIpx = s[5 + c].x * INV_K2, cIpy = s[5 + c].y * INV_K2;
                float ax = (cIpx - mIx * mpx) * ivx;
                float ay = (cIpy - mIy * mpy) * ivy;
                ab[c].x = ax;                 ab[c].y = ay;
                ab[3 + c].x = mpx - ax * mIx; ab[3 + c].y = mpy - ay * mIy;
            }
        }

        float tq[6], wv[6];
#pragma unroll
        for (int q = 0; q < 6; q++) {
            tq[q] = ab[q].x + ab[q].y;
            wv[q] = iscan(tq[q], lane);
            if (lane == 31) s_wtot[bu][q][warp] = wv[q];
        }
        __syncthreads();
#pragma unroll
        for (int q = 0; q < 6; q++) {
            float carry = 0.f;
#pragma unroll
            for (int w = 0; w < 7; w++) if (w < warp) carry += s_wtot[bu][q][w];
            float ex = wv[q] - tq[q] + carry;
            float2 pr;
            pr.x = ex + ab[q].x;
            pr.y = pr.x + ab[q].y;
            ((float2*)s_pref[bu][q])[tid] = pr;
        }
        __syncthreads();

        const int x0 = 2 * tid, x1 = x0 + 1;
        const int h0 = (x0 + RAD > WW - 1) ? (WW - 1) : (x0 + RAD);
        const int h1 = (x1 + RAD > WW - 1) ? (WW - 1) : (x1 + RAD);
#pragma unroll
        for (int q = 0; q < 6; q++) {
            float lo0 = (x0 >= RAD + 1) ? s_pref[bu][q][x0 - RAD - 1] : 0.f;
            float lo1 = (x1 >= RAD + 1) ? s_pref[bu][q][x1 - RAD - 1] : 0.f;
            __half2 hv = __floats2half2_rn(s_pref[bu][q][h0] - lo0,
                                           s_pref[bu][q][h1] - lo1);
            ((__half2*)g_hsum2[q])[off] = hv;
        }

        if (hl) {
#pragma unroll
            for (int q = 0; q < 8; q++) { s[q].x += ldv[q].x; s[q].y += ldv[q].y; }
        }
        if (ht) {
#pragma unroll
            for (int q = 0; q < 8; q++) { s[q].x -= trv[q].x; s[q].y -= trv[q].y; }
        }
    }
}

// ============================================================================
// K3: vertical running sums on fp16 hsum2 — COLUMN-SPLIT (scan-free, safe):
// 128 thr x 2 cols (half2 loads, fp32 accum), 256-col half per block.
// grid (2, HH/SEG, BATCH*3) = 1536 blocks (2x warps vs R12).
// ============================================================================
__global__ __launch_bounds__(128) void k_v2(float* __restrict__ out) {
    const int t  = blockIdx.x * 128 + threadIdx.x;   // half2 col index 0..255
    const int zc = blockIdx.z;
    const int b  = zc / 3;
    const int c  = zc - b * 3;
    const int r0 = blockIdx.y * SEG;
    const int base = b * (PLANE / 2) + t;            // half2 index

    const __half2* __restrict__ pa = (const __half2*)g_hsum2[c];
    const __half2* __restrict__ pb = (const __half2*)g_hsum2[3 + c];
    const __half2* __restrict__ pg = (const __half2*)g_gray;
    float2* __restrict__ po = (float2*)(out + (size_t)zc * PLANE);

    float2 sa = make_float2(0.f, 0.f);
    float2 sb = make_float2(0.f, 0.f);

    const int jstart = (r0 - RAD < 0) ? 0 : (r0 - RAD);
#pragma unroll 4
    for (int j = jstart; j <= r0 + RAD; j++) {
        const int off = base + j * W2;
        float2 va = __half22float2(pa[off]);
        float2 vb = __half22float2(pb[off]);
        sa.x += va.x; sa.y += va.y;
        sb.x += vb.x; sb.y += vb.y;
    }

#pragma unroll 4
    for (int i = 0; i < SEG; i++) {
        const int row = r0 + i;
        const int off = base + row * W2;

        const int lead  = row + RAD + 1;
        const int trail = row - RAD;
        const bool hl = lead < HH;
        const bool ht = trail >= 0;
        float2 la, lb, ta, tb;
        if (hl) {
            const int lo = base + lead * W2;
            la = __half22float2(pa[lo]); lb = __half22float2(pb[lo]);
        }
        if (ht) {
            const int to = base + trail * W2;
            ta = __half22float2(pa[to]); tb = __half22float2(pb[to]);
        }

        const float2 gr = __half22float2(pg[off]);
        float2 o;
        o.x = (sa.x * INV_K2) * gr.x + sb.x * INV_K2;
        o.y = (sa.y * INV_K2) * gr.y + sb.y * INV_K2;
        po[row * W2 + t] = o;

        if (hl) {
            sa.x += la.x; sa.y += la.y;
            sb.x += lb.x; sb.y += lb.y;
        }
        if (ht) {
            sa.x -= ta.x; sa.y -= ta.y;
            sb.x -= tb.x; sb.y -= tb.y;
        }
    }
}

// ============================================================================
extern "C" void kernel_launch(void* const* d_in, const int* in_sizes, int n_in,
                              void* d_out, int out_size) {
    const float* guide = (const float*)d_in[0];
    const float* input = (const float*)d_in[1];
    float* out = (float*)d_out;

    k_h1<<<BATCH * HH / 4, 128>>>(guide, input);
    k_vh<<<dim3(HH / SEGV, BATCH), 256>>>();
    k_v2<<<dim3(2, HH / SEG, BATCH * 3), 128>>>(out);
}